// round 12
// baseline (speedup 1.0000x reference)
#include <cuda_runtime.h>
#include <math.h>

#define NB 32
#define NT 512
#define NE 300
#define NH 512
#define NG 2048   // 4*NH

#define NCTA_B 128
#define THR_B  512

#define HS_STRIDE 36          // floats per h row (32 used; 144B = 16B-aligned rows)
#define US_STRIDE 18          // u64 per U row (16 used, even)
#define RED_ROW   520         // floats per kt row (512 used)

typedef unsigned long long u64;

// ---------------------------------------------------------------------------
__device__ __forceinline__ u64 pack2(float lo, float hi) {
    u64 r; asm("mov.b64 %0, {%1,%2};" : "=l"(r) : "f"(lo), "f"(hi)); return r;
}
__device__ __forceinline__ void fma2(u64& d, u64 a, u64 b) {
    asm("fma.rn.f32x2 %0, %1, %2, %0;" : "+l"(d) : "l"(a), "l"(b));
}
__device__ __forceinline__ float2 unpack2(u64 v) {
    float2 f; asm("mov.b64 {%0,%1}, %2;" : "=f"(f.x), "=f"(f.y) : "l"(v)); return f;
}

__device__ __forceinline__ float fast_sig(float x) {
    float e = __expf(-x);
    return __fdividef(1.f, 1.f + e);
}
__device__ __forceinline__ float fast_tanh(float x) {
    float e = __expf(2.f * x);              // inf-safe
    return 1.f - 2.f * __fdividef(1.f, e + 1.f);
}

__device__ __forceinline__ void bar_release_add(unsigned int* p) {
    asm volatile("red.release.gpu.global.add.u32 [%0], %1;"
                 :: "l"(p), "r"(1u) : "memory");
}
__device__ __forceinline__ unsigned int bar_acquire_ld(unsigned int* p) {
    unsigned int v;
    asm volatile("ld.acquire.gpu.global.u32 %0, [%1];"
                 : "=r"(v) : "l"(p) : "memory");
    return v;
}

// Scratch (device globals)
// xz layout: [t][j][b][gate]  (one float4 per (t,j,b))
__device__ float g_xz[(size_t)NT * NH * NB * 4];
__device__ float g_h[2][NH * NB];              // ping-pong h, [k][b]
__device__ unsigned int g_bar;

// ---------------------------------------------------------------------------
// Kernel A (R5 version — best measured): z = emb[tok] @ W + b
// Tiles 64(M)x64(N), BK=25. Also zeroes g_h / g_bar.
// ---------------------------------------------------------------------------
__global__ __launch_bounds__(256) void xz_kernel(
    const int* __restrict__ tokens, const float* __restrict__ emb,
    const float* __restrict__ W, const float* __restrict__ bias)
{
    __shared__ float As[25 * 68];
    __shared__ u64   Bs2[25 * 68];
    __shared__ int   toks[64];

    int tid = threadIdx.x;
    int m0 = blockIdx.y * 64;
    int n0 = blockIdx.x * 64;

    if (blockIdx.x == 0 && blockIdx.y < 32) {
        int i = blockIdx.y * 256 + tid;
        ((float4*)g_h)[i] = make_float4(0.f, 0.f, 0.f, 0.f);
        if (i == 0) g_bar = 0u;
    }

    if (tid < 64) {
        int m = m0 + tid;
        toks[tid] = tokens[(m & 31) * NT + (m >> 5)];
    }
    __syncthreads();

    int tm = tid & 15, tn = tid >> 4;
    u64 acc2[2][4];
    #pragma unroll
    for (int p = 0; p < 2; ++p)
        #pragma unroll
        for (int j = 0; j < 4; ++j) acc2[p][j] = 0ull;

    for (int k0 = 0; k0 < NE; k0 += 25) {
        for (int idx = tid; idx < 64 * 25; idx += 256) {
            int m = idx / 25, kk = idx - m * 25;
            As[kk * 68 + m] = emb[(size_t)toks[m] * NE + k0 + kk];
        }
        for (int idx = tid; idx < 25 * 64; idx += 256) {
            int kk = idx >> 6, n = idx & 63;
            float w = W[(size_t)(k0 + kk) * NG + n0 + n];
            Bs2[kk * 68 + n] = pack2(w, w);
        }
        __syncthreads();

        #pragma unroll
        for (int kk = 0; kk < 25; ++kk) {
            float4 av = *(const float4*)&As[kk * 68 + tm * 4];
            ulonglong2 b01 = *(const ulonglong2*)&Bs2[kk * 68 + tn * 4];
            ulonglong2 b23 = *(const ulonglong2*)&Bs2[kk * 68 + tn * 4 + 2];
            u64 ap[2] = { pack2(av.x, av.y), pack2(av.z, av.w) };
            u64 bd[4] = { b01.x, b01.y, b23.x, b23.y };
            #pragma unroll
            for (int p = 0; p < 2; ++p)
                #pragma unroll
                for (int j = 0; j < 4; ++j)
                    fma2(acc2[p][j], ap[p], bd[j]);
        }
        __syncthreads();
    }

    #pragma unroll
    for (int j = 0; j < 4; ++j) {
        int n = n0 + tn * 4 + j;
        int gate = n >> 9, col = n & 511;
        float bb = bias[n];
        #pragma unroll
        for (int p = 0; p < 2; ++p) {
            float2 v = unpack2(acc2[p][j]);
            int mi0 = m0 + tm * 4 + p * 2;
            int t0 = mi0 >> 5, b0 = mi0 & 31;
            int t1 = (mi0 + 1) >> 5, b1 = (mi0 + 1) & 31;
            __stcs(&g_xz[(((size_t)t0 * NH + col) * NB + b0) * 4 + gate], v.x + bb);
            __stcs(&g_xz[(((size_t)t1 * NH + col) * NB + b1) * 4 + gate], v.y + bb);
        }
    }
}

// ---------------------------------------------------------------------------
// Kernel B: persistent LSTM, warp-autonomous step structure.
// 128 CTAs x 512 thr. Warp kt owns K rows {kt+16i}: copies ONLY those rows
// (warp-local, no CTA sync), GEMMs, stores red[kt]. One __syncthreads per
// step; gate warps fold the 16-way reduce + gates; tid0 polls the global
// counter and broadcasts via an smem flag that warps spin on independently.
// ---------------------------------------------------------------------------
__global__ __launch_bounds__(THR_B) void lstm_kernel(
    const float* __restrict__ U, float* __restrict__ out)
{
    extern __shared__ float sm[];
    u64*   us2 = (u64*)sm;                      // [512][US_STRIDE] u64
    float* hs  = (float*)(us2 + NH * US_STRIDE);// [512][HS_STRIDE]
    float* red = hs + NH * HS_STRIDE;           // [16][RED_ROW]
    volatile int* sflag = (volatile int*)(red + 16 * RED_ROW);

    int tid = threadIdx.x;
    int cta = blockIdx.x;
    int j0 = cta * 4;

    // U slice as duplicated pairs: col c = gate*4+jj -> U[k][gate*512+j0+jj]
    for (int idx = tid; idx < NH * 16; idx += THR_B) {
        int k = idx >> 4, c = idx & 15;
        int col = (c >> 2) * NH + j0 + (c & 3);
        float u = U[(size_t)k * NG + col];
        us2[k * US_STRIDE + c] = pack2(u, u);
    }
    if (tid == 0) *sflag = 0;                   // step 0 ready (h=0 preset)
    __syncthreads();

    int kt = tid >> 5, lane = tid & 31;
    int b0 = (lane & 7) * 4;                    // 8 b-tiles of 4
    int c0 = (lane >> 3) * 4;                   // 4 c-tiles of 4 (even u64 idx)
    int jj = tid >> 5, bb = tid & 31;           // gates mapping (tid<128)
    float creg = 0.f;

    for (int t = 0; t < NT; ++t) {
        int parity = t & 1;

        // xz prefetch (gate threads) — issued before the wait, used after GEMM
        float4 xv = make_float4(0.f, 0.f, 0.f, 0.f);
        if (tid < 128)
            xv = __ldcs((const float4*)&g_xz[(((size_t)t * NH + j0 + jj) * NB + bb) * 4]);

        // step-ready wait: tid0 polls global counter, others spin on smem flag
        if (tid == 0) {
            unsigned tgt = 128u * (unsigned)t;
            while (bar_acquire_ld(&g_bar) < tgt) { }
            *sflag = t;
        } else if (lane == 0) {
            while (*sflag < t) { }
        }
        __syncwarp();

        // warp-local copy of OWN rows {kt+16i}: 8 ldcg.128 + 8 STS.128 / lane
        const float4* gh4 = (const float4*)g_h[parity];
        float4 v[8];
        #pragma unroll
        for (int r = 0; r < 8; ++r) {
            int linear = r * 32 + lane;
            int row = kt + 16 * (linear >> 3);
            v[r] = __ldcg(gh4 + row * 8 + (linear & 7));
        }
        #pragma unroll
        for (int r = 0; r < 8; ++r) {
            int linear = r * 32 + lane;
            int row = kt + 16 * (linear >> 3);
            *(float4*)(hs + row * HS_STRIDE + (linear & 7) * 4) = v[r];
        }
        __syncwarp();

        // GEMM over own 32 rows: per k, 1 h-LDS.128 + 2 U-LDS.128 -> 8 fma2
        u64 acc2[2][4];
        #pragma unroll
        for (int p = 0; p < 2; ++p)
            #pragma unroll
            for (int j = 0; j < 4; ++j) acc2[p][j] = 0ull;

        #pragma unroll 8
        for (int i = 0; i < 32; ++i) {
            int kk = kt + 16 * i;
            float4 hv = *(const float4*)(hs + kk * HS_STRIDE + b0);
            const u64* urow = us2 + kk * US_STRIDE + c0;
            ulonglong2 ua = *(const ulonglong2*)urow;
            ulonglong2 ub = *(const ulonglong2*)(urow + 2);
            u64 hp[2] = { pack2(hv.x, hv.y), pack2(hv.z, hv.w) };
            u64 up[4] = { ua.x, ua.y, ub.x, ub.y };
            #pragma unroll
            for (int p = 0; p < 2; ++p)
                #pragma unroll
                for (int j = 0; j < 4; ++j)
                    fma2(acc2[p][j], hp[p], up[j]);
        }

        // store partials: red[kt][(c0+j)*32 + b0]
        #pragma unroll
        for (int j = 0; j < 4; ++j) {
            float2 v0 = unpack2(acc2[0][j]);
            float2 v1 = unpack2(acc2[1][j]);
            *(float4*)(red + kt * RED_ROW + (c0 + j) * 32 + b0) =
                make_float4(v0.x, v0.y, v1.x, v1.y);
        }
        __syncthreads();          // red complete (the ONE per-step CTA sync)

        // Gate warps: fold 16-way reduce + gates + publish
        if (tid < 128) {
            float zi = xv.x, zf = xv.y, zg = xv.z, zo = xv.w;
            #pragma unroll
            for (int q = 0; q < 16; ++q) {
                const float* rp = red + q * RED_ROW + bb;
                zi += rp[(0 * 4 + jj) * 32];
                zf += rp[(1 * 4 + jj) * 32];
                zg += rp[(2 * 4 + jj) * 32];
                zo += rp[(3 * 4 + jj) * 32];
            }

            float ig = fast_sig(zi);
            float fg = fast_sig(zf);
            float gg = fast_tanh(zg);
            float og = fast_sig(zo);

            float cn = fg * creg + ig * gg;
            creg = cn;
            float hn = og * fast_tanh(cn);

            if (t == NT - 1) {
                out[bb * NH + (j0 + jj)] = hn;             // hidden [B,H]
                out[NB * NH + bb * NH + (j0 + jj)] = cn;   // cell   [B,H]
            } else {
                __stcg(&g_h[parity ^ 1][(j0 + jj) * NB + bb], hn);
                asm volatile("bar.sync 1, 128;" ::: "memory");
                if (tid == 0) bar_release_add(&g_bar);     // publish h[t+1]
            }
        }
    }
}

// ---------------------------------------------------------------------------
extern "C" void kernel_launch(void* const* d_in, const int* in_sizes, int n_in,
                              void* d_out, int out_size) {
    const int*   tokens = (const int*)d_in[0];
    const float* emb    = (const float*)d_in[1];
    const float* W      = (const float*)d_in[2];
    const float* U      = (const float*)d_in[3];
    const float* bias   = (const float*)d_in[4];
    float* out = (float*)d_out;

    dim3 ga(NG / 64, (NB * NT) / 64);   // (32, 256)
    xz_kernel<<<ga, 256>>>(tokens, emb, W, bias);

    int smem = (int)(NH * US_STRIDE * sizeof(u64) +
                     (NH * HS_STRIDE + 16 * RED_ROW) * sizeof(float) + 16);
    cudaFuncSetAttribute(lstm_kernel, cudaFuncAttributeMaxDynamicSharedMemorySize, smem);
    lstm_kernel<<<NCTA_B, THR_B, smem>>>(U, out);
}

// round 13
// speedup vs baseline: 1.3268x; 1.3268x over previous
#include <cuda_runtime.h>
#include <math.h>

#define NB 32
#define NT 512
#define NE 300
#define NH 512
#define NG 2048   // 4*NH

#define NCTA_B 128
#define THR_B  512

#define HS_STRIDE 36          // floats per h row (32 used)
#define US_STRIDE 18          // u64 per U row (16 used)
#define RED_ROW   520         // floats per kt row (512 used)

#define GATE_STRIDE (NH * NB)   // 16384 floats between gates in g_xz

typedef unsigned long long u64;

// ---------------------------------------------------------------------------
__device__ __forceinline__ u64 pack2(float lo, float hi) {
    u64 r; asm("mov.b64 %0, {%1,%2};" : "=l"(r) : "f"(lo), "f"(hi)); return r;
}
__device__ __forceinline__ void fma2(u64& d, u64 a, u64 b) {
    asm("fma.rn.f32x2 %0, %1, %2, %0;" : "+l"(d) : "l"(a), "l"(b));
}
__device__ __forceinline__ float2 unpack2(u64 v) {
    float2 f; asm("mov.b64 {%0,%1}, %2;" : "=f"(f.x), "=f"(f.y) : "l"(v)); return f;
}

__device__ __forceinline__ float fast_sig(float x) {
    float e = __expf(-x);
    return __fdividef(1.f, 1.f + e);
}
__device__ __forceinline__ float fast_tanh(float x) {
    float e = __expf(2.f * x);              // inf-safe
    return 1.f - 2.f * __fdividef(1.f, e + 1.f);
}

__device__ __forceinline__ void bar_release_add(unsigned int* p) {
    asm volatile("red.release.gpu.global.add.u32 [%0], %1;"
                 :: "l"(p), "r"(1u) : "memory");
}
__device__ __forceinline__ unsigned int bar_acquire_ld(unsigned int* p) {
    unsigned int v;
    asm volatile("ld.acquire.gpu.global.u32 %0, [%1];"
                 : "=r"(v) : "l"(p) : "memory");
    return v;
}

// Scratch (device globals)
// xz layout: [t][gate][j][b]  (b contiguous -> coalesced writes AND reads)
__device__ float g_xz[(size_t)NT * 4 * NH * NB];
__device__ float g_h[2][NH * NB];              // ping-pong h, [k][b]
__device__ unsigned int g_bar;

// ---------------------------------------------------------------------------
// Kernel A: z[t][n][b] = sum_k emb[tok(b,t)][k] * W[k][n] + bias[n]
// Tiles 64(M)x64(N), BK=25 (R5 mainloop). NEW: epilogue stages the tile in
// smem and emits fully-coalesced STG.128 into [t][gate][j][b] layout.
// Also zeroes g_h / g_bar.
// ---------------------------------------------------------------------------
__global__ __launch_bounds__(256) void xz_kernel(
    const int* __restrict__ tokens, const float* __restrict__ emb,
    const float* __restrict__ W, const float* __restrict__ bias)
{
    __shared__ float As[25 * 68];
    __shared__ u64   Bs2[25 * 68];
    __shared__ int   toks[64];
    __shared__ float stage[64 * 68];     // [n][m], stride 68

    int tid = threadIdx.x;
    int m0 = blockIdx.y * 64;
    int n0 = blockIdx.x * 64;

    if (blockIdx.x == 0 && blockIdx.y < 32) {
        int i = blockIdx.y * 256 + tid;
        ((float4*)g_h)[i] = make_float4(0.f, 0.f, 0.f, 0.f);
        if (i == 0) g_bar = 0u;
    }

    if (tid < 64) {
        int m = m0 + tid;
        toks[tid] = tokens[(m & 31) * NT + (m >> 5)];
    }
    __syncthreads();

    int tm = tid & 15, tn = tid >> 4;
    u64 acc2[2][4];
    #pragma unroll
    for (int p = 0; p < 2; ++p)
        #pragma unroll
        for (int j = 0; j < 4; ++j) acc2[p][j] = 0ull;

    for (int k0 = 0; k0 < NE; k0 += 25) {
        for (int idx = tid; idx < 64 * 25; idx += 256) {
            int m = idx / 25, kk = idx - m * 25;
            As[kk * 68 + m] = emb[(size_t)toks[m] * NE + k0 + kk];
        }
        for (int idx = tid; idx < 25 * 64; idx += 256) {
            int kk = idx >> 6, n = idx & 63;
            float w = W[(size_t)(k0 + kk) * NG + n0 + n];
            Bs2[kk * 68 + n] = pack2(w, w);
        }
        __syncthreads();

        #pragma unroll
        for (int kk = 0; kk < 25; ++kk) {
            float4 av = *(const float4*)&As[kk * 68 + tm * 4];
            ulonglong2 b01 = *(const ulonglong2*)&Bs2[kk * 68 + tn * 4];
            ulonglong2 b23 = *(const ulonglong2*)&Bs2[kk * 68 + tn * 4 + 2];
            u64 ap[2] = { pack2(av.x, av.y), pack2(av.z, av.w) };
            u64 bd[4] = { b01.x, b01.y, b23.x, b23.y };
            #pragma unroll
            for (int p = 0; p < 2; ++p)
                #pragma unroll
                for (int j = 0; j < 4; ++j)
                    fma2(acc2[p][j], ap[p], bd[j]);
        }
        __syncthreads();
    }

    // ---- epilogue: stage (bias folded) -> coalesced STG.128 ----
    #pragma unroll
    for (int j = 0; j < 4; ++j) {
        int n = tn * 4 + j;
        float bb = bias[n0 + n];
        #pragma unroll
        for (int p = 0; p < 2; ++p) {
            float2 v = unpack2(acc2[p][j]);
            int m = tm * 4 + p * 2;
            stage[n * 68 + m]     = v.x + bb;
            stage[n * 68 + m + 1] = v.y + bb;
        }
    }
    __syncthreads();

    {
        int t0 = m0 >> 5;                    // first t of this tile
        int gate = n0 >> 9, col0 = n0 & 511;
        int s = tid >> 1, half = tid & 1;    // s: 0..127 = (tl, col)
        int tl = s >> 6, col = s & 63;
        const float4* src = (const float4*)(stage + col * 68 + tl * 32 + half * 16);
        float4* dst = (float4*)&g_xz[(((size_t)(t0 + tl) * 4 + gate) * NH
                                      + (col0 + col)) * NB + half * 16];
        #pragma unroll
        for (int q = 0; q < 4; ++q)
            __stcs(dst + q, src[q]);
    }
}

// ---------------------------------------------------------------------------
// Kernel B: persistent LSTM (R5 structure — frozen). 128 CTAs x 512 thr;
// CTA owns 4 h-cols across 4 gates. Warp = one kt slice (interleaved K,
// stride 16). Thread tile 4b x 4c. Chunk-pipelined h broadcast.
// Only change vs R5: xz read = 4 coalesced scalar loads (new layout).
// ---------------------------------------------------------------------------
__global__ __launch_bounds__(THR_B) void lstm_kernel(
    const float* __restrict__ U, float* __restrict__ out)
{
    extern __shared__ float sm[];
    u64*   us2 = (u64*)sm;                      // [512][US_STRIDE] u64
    float* hs  = (float*)(us2 + NH * US_STRIDE);// [512][HS_STRIDE]
    float* red = hs + NH * HS_STRIDE;           // [16][RED_ROW]
    float* zs  = red + 16 * RED_ROW;            // [512]
    float* cs  = zs + 512;                      // [128]

    int tid = threadIdx.x;
    int cta = blockIdx.x;
    int j0 = cta * 4;

    // Load U slice as duplicated pairs: col c = gate*4+jj -> U[k][gate*512+j0+jj]
    for (int idx = tid; idx < NH * 16; idx += THR_B) {
        int k = idx >> 4, c = idx & 15;
        int col = (c >> 2) * NH + j0 + (c & 3);
        float u = U[(size_t)k * NG + col];
        us2[k * US_STRIDE + c] = pack2(u, u);
    }
    if (tid < 128) cs[tid] = 0.f;
    __syncthreads();

    // warp = kt (16 K-slices); thread tile 4 batches x 4 cols
    int kt = tid >> 5;                          // warp id
    int ot = tid & 31;
    int b0 = (ot & 7) * 4;                      // 8 b-tiles of 4
    int c0 = (ot >> 3) * 4;                     // 4 c-tiles of 4
    int jj = tid >> 5, bb = tid & 31;           // gates mapping (tid<128)

    for (int t = 0; t < NT; ++t) {
        int parity = t & 1;

        // Prefetch xz: 4 coalesced scalar loads (one per gate)
        float x0 = 0.f, x1 = 0.f, x2 = 0.f, x3 = 0.f;
        if (tid < 128) {
            size_t base = (((size_t)t * 4) * NH + (j0 + jj)) * NB + bb;
            x0 = __ldcs(&g_xz[base]);
            x1 = __ldcs(&g_xz[base + 1 * GATE_STRIDE]);
            x2 = __ldcs(&g_xz[base + 2 * GATE_STRIDE]);
            x3 = __ldcs(&g_xz[base + 3 * GATE_STRIDE]);
        }

        const float4* gh4 = (const float4*)g_h[parity];

        // ---- chunk 0 copy (rows 0..127 = 1024 float4, 2 per thread) ----
        #pragma unroll
        for (int r = 0; r < 2; ++r) {
            int f = r * 512 + tid;
            float4 v = __ldcg(gh4 + f);
            int base = f * 4;
            *(float4*)(hs + (base >> 5) * HS_STRIDE + (base & 31)) = v;
        }
        __syncthreads();

        u64 acc2[2][4];
        #pragma unroll
        for (int i = 0; i < 2; ++i)
            #pragma unroll
            for (int j = 0; j < 4; ++j) acc2[i][j] = 0ull;

        // ---- pipelined chunks: prefetch next, GEMM current ----
        #pragma unroll
        for (int c = 0; c < 4; ++c) {
            float4 pre[2];
            if (c < 3) {
                #pragma unroll
                for (int r = 0; r < 2; ++r)
                    pre[r] = __ldcg(gh4 + (c + 1) * 1024 + r * 512 + tid);
            }

            #pragma unroll
            for (int i = 0; i < 8; ++i) {
                int kk = 128 * c + 16 * i + kt;
                float4 hv = *(const float4*)(hs + kk * HS_STRIDE + b0);
                const u64* urow = us2 + kk * US_STRIDE + c0;
                ulonglong2 ua = *(const ulonglong2*)urow;
                ulonglong2 ub = *(const ulonglong2*)(urow + 2);
                u64 hp[2] = { pack2(hv.x, hv.y), pack2(hv.z, hv.w) };
                u64 up[4] = { ua.x, ua.y, ub.x, ub.y };
                #pragma unroll
                for (int p = 0; p < 2; ++p)
                    #pragma unroll
                    for (int j = 0; j < 4; ++j)
                        fma2(acc2[p][j], hp[p], up[j]);
            }

            if (c < 3) {
                #pragma unroll
                for (int r = 0; r < 2; ++r) {
                    int f = (c + 1) * 1024 + r * 512 + tid;
                    int base = f * 4;
                    *(float4*)(hs + (base >> 5) * HS_STRIDE + (base & 31)) = pre[r];
                }
                __syncthreads();
            }
        }

        // K-split partials: red[kt][c*32 + b]
        #pragma unroll
        for (int j = 0; j < 4; ++j) {
            float2 v0 = unpack2(acc2[0][j]);
            float2 v1 = unpack2(acc2[1][j]);
            *(float4*)(red + kt * RED_ROW + (c0 + j) * 32 + b0) =
                make_float4(v0.x, v0.y, v1.x, v1.y);
        }
        __syncthreads();

        // 512 outputs / 512 threads: 1 each
        {
            int o = tid;
            float s = 0.f;
            #pragma unroll
            for (int q = 0; q < 16; ++q) s += red[q * RED_ROW + o];
            zs[o] = s;
        }
        __syncthreads();

        // Gates + state update (thread = (jj, bb), 128 threads)
        if (tid < 128) {
            float zi = zs[(0 * 4 + jj) * 32 + bb] + x0;
            float zf = zs[(1 * 4 + jj) * 32 + bb] + x1;
            float zg = zs[(2 * 4 + jj) * 32 + bb] + x2;
            float zo = zs[(3 * 4 + jj) * 32 + bb] + x3;

            float ig = fast_sig(zi);
            float fg = fast_sig(zf);
            float gg = fast_tanh(zg);
            float og = fast_sig(zo);

            float cn = fg * cs[tid] + ig * gg;
            cs[tid] = cn;
            float hn = og * fast_tanh(cn);

            if (t == NT - 1) {
                out[bb * NH + (j0 + jj)] = hn;             // hidden [B,H]
                out[NB * NH + bb * NH + (j0 + jj)] = cn;   // cell   [B,H]
            } else {
                __stcg(&g_h[parity ^ 1][(j0 + jj) * NB + bb], hn);
            }
        }

        // Grid-wide barrier: release-increment, acquire-poll
        if (t < NT - 1) {
            __syncthreads();
            if (tid == 0) {
                bar_release_add(&g_bar);
                unsigned target = (unsigned)NCTA_B * (unsigned)(t + 1);
                while (bar_acquire_ld(&g_bar) < target) { }
            }
            __syncthreads();
        }
    }
}

// ---------------------------------------------------------------------------
extern "C" void kernel_launch(void* const* d_in, const int* in_sizes, int n_in,
                              void* d_out, int out_size) {
    const int*   tokens = (const int*)d_in[0];
    const float* emb    = (const float*)d_in[1];
    const float* W      = (const float*)d_in[2];
    const float* U      = (const float*)d_in[3];
    const float* bias   = (const float*)d_in[4];
    float* out = (float*)d_out;

    dim3 ga(NG / 64, (NB * NT) / 64);   // (32, 256)
    xz_kernel<<<ga, 256>>>(tokens, emb, W, bias);

    int smem = (int)(NH * US_STRIDE * sizeof(u64) +
                     (NH * HS_STRIDE + 16 * RED_ROW + 512 + 128) * sizeof(float));
    cudaFuncSetAttribute(lstm_kernel, cudaFuncAttributeMaxDynamicSharedMemorySize, smem);
    lstm_kernel<<<NCTA_B, THR_B, smem>>>(U, out);
}